// round 15
// baseline (speedup 1.0000x reference)
#include <cuda_runtime.h>

// Depth-4 path signature, C=10, L=512. ONE fused kernel, symmetric merge:
//  CTA (b,0)=chunk A [0,256), CTA (b,1)=chunk B [256,511). Both run the
//  proven register-packed f32x2 Chen scan. Each exports its tables
//  (L1|L2|L3, 1110 fl) plus the L4 half the OTHER CTA merges (transposed,
//  coalesced u64), exchanges flags, then merges the 500 rows it holds in
//  registers and writes half the output via smem staging (coalesced).

#define SIG_C 10
#define SIG_L 512
#define SIG_NSTEP 511
#define SIG_OUT 11110
#define SIG_MAXB 128
#define CHUNK0 256
#define PBLK 6110   // exchange block: 1110 tables + 5000 L4-half floats

typedef unsigned long long u64;

__device__ __align__(16) float g_part[SIG_MAXB * 2 * PBLK];
__device__ int g_flag[SIG_MAXB * 2];   // zero-init; self-resetting

__device__ __forceinline__ u64 ffma2(u64 a, u64 b, u64 c) {
    u64 d; asm("fma.rn.f32x2 %0, %1, %2, %3;" : "=l"(d) : "l"(a), "l"(b), "l"(c)); return d;
}
__device__ __forceinline__ u64 fmul2(u64 a, u64 b) {
    u64 d; asm("mul.rn.f32x2 %0, %1, %2;" : "=l"(d) : "l"(a), "l"(b)); return d;
}
__device__ __forceinline__ u64 fadd2(u64 a, u64 b) {
    u64 d; asm("add.rn.f32x2 %0, %1, %2;" : "=l"(d) : "l"(a), "l"(b)); return d;
}
__device__ __forceinline__ u64 pack2(float lo, float hi) {
    u64 d; asm("mov.b64 %0, {%1, %2};" : "=l"(d) : "f"(lo), "f"(hi)); return d;
}
__device__ __forceinline__ void unpack2(u64 a, float& lo, float& hi) {
    asm("mov.b64 {%0, %1}, %2;" : "=f"(lo), "=f"(hi) : "l"(a));
}

__global__ __launch_bounds__(512, 1)
void sig_fused_kernel(const float* __restrict__ path, float* __restrict__ out) {
    __shared__ __align__(16) float dxs[CHUNK0 * 12];
    __shared__ __align__(16) float At[1110];   // other chunk's tables
    __shared__ __align__(16) float Ot[1110];   // own tables stash (CTA1 only)
    __shared__ __align__(16) float stage[5610];

    const int b = blockIdx.x >> 1;
    const int c = blockIdx.x & 1;
    const int start = c ? CHUNK0 : 0;
    const int n = c ? (SIG_NSTEP - CHUNK0) : CHUNK0;   // 255 : 256
    const int tid = threadIdx.x;
    const float* prow = path + (size_t)b * SIG_L * SIG_C + (size_t)start * SIG_C;

    for (int i = tid; i < n * SIG_C; i += 512) {
        int t = i / SIG_C;
        int cc = i - t * SIG_C;
        dxs[t * 12 + cc] = prow[(t + 1) * SIG_C + cc] - prow[t * SIG_C + cc];
    }
    __syncthreads();

    const bool active = (tid < 500);
    const int i1 = (tid / 100) % 5;
    const int i2 = (tid / 10) % 10;
    const int i3 = tid % 10;

    const u64 c1_2  = pack2(0.5f, 0.5f);
    const u64 c1_6  = pack2(1.0f / 6.0f, 1.0f / 6.0f);
    const u64 c1_24 = pack2(1.0f / 24.0f, 1.0f / 24.0f);

    u64 l1v2 = 0, l2v2 = 0, l3_2 = 0;
    u64 l4lo[5], l4hi[5];
#pragma unroll
    for (int j = 0; j < 5; ++j) { l4lo[j] = 0; l4hi[j] = 0; }

    if (active) {
        // ---- init with exp(dx_0) ----  (verbatim)
        {
            float Bv = dxs[i2], Cv = dxs[i3];
            u64 A2 = pack2(dxs[i1], dxs[i1 + 5]);
            float d23 = Bv * Cv;
            u64 d23_2 = pack2(d23, d23);
            u64 B2 = pack2(Bv, Bv);
            l1v2 = A2;
            l2v2 = fmul2(fmul2(A2, B2), c1_2);
            l3_2 = fmul2(fmul2(A2, d23_2), c1_6);
            u64 c4 = fmul2(l3_2, pack2(0.25f, 0.25f));
            float clo, chi; unpack2(c4, clo, chi);
            u64 clo2 = pack2(clo, clo), chi2 = pack2(chi, chi);
            ulonglong2 va = *reinterpret_cast<const ulonglong2*>(dxs);
            ulonglong2 vb = *reinterpret_cast<const ulonglong2*>(dxs + 4);
            u64 vc = *reinterpret_cast<const u64*>(dxs + 8);
            l4lo[0] = fmul2(clo2, va.x); l4hi[0] = fmul2(chi2, va.x);
            l4lo[1] = fmul2(clo2, va.y); l4hi[1] = fmul2(chi2, va.y);
            l4lo[2] = fmul2(clo2, vb.x); l4hi[2] = fmul2(chi2, vb.x);
            l4lo[3] = fmul2(clo2, vb.y); l4hi[3] = fmul2(chi2, vb.y);
            l4lo[4] = fmul2(clo2, vc);   l4hi[4] = fmul2(chi2, vc);
        }

        // ---- barrier-free packed scan ----  (verbatim)
        const float* q1 = dxs + i1 + 12;
        const float* q2 = dxs + i2 + 12;
        const float* q3 = dxs + i3 + 12;
        const char*  qv = reinterpret_cast<const char*>(dxs) + 48;

#pragma unroll 4
        for (int t = 1; t < n; ++t) {
            float A_lo = *q1;
            float A_hi = q1[5];
            float Bv = *q2;
            float Cv = *q3;
            ulonglong2 va = *reinterpret_cast<const ulonglong2*>(qv);
            ulonglong2 vb = *reinterpret_cast<const ulonglong2*>(qv + 16);
            u64 vc = *reinterpret_cast<const u64*>(qv + 32);
            q1 += 12; q2 += 12; q3 += 12; qv += 48;

            float d23 = Bv * Cv;
            u64 A2 = pack2(A_lo, A_hi);
            u64 d23_2 = pack2(d23, d23);
            u64 C2 = pack2(Cv, Cv);
            u64 B2 = pack2(Bv, Bv);
            u64 t1 = fmul2(A2, d23_2);
            u64 uu = fmul2(l2v2, C2);
            u64 vv = fmul2(l1v2, d23_2);
            u64 coef = ffma2(c1_24, t1, ffma2(c1_2, uu, ffma2(c1_6, vv, l3_2)));
            l3_2 = ffma2(c1_6, t1, ffma2(c1_2, vv, fadd2(l3_2, uu)));
            l2v2 = ffma2(ffma2(c1_2, A2, l1v2), B2, l2v2);
            l1v2 = fadd2(l1v2, A2);

            float clo, chi; unpack2(coef, clo, chi);
            u64 clo2 = pack2(clo, clo), chi2 = pack2(chi, chi);
            l4lo[0] = ffma2(clo2, va.x, l4lo[0]); l4hi[0] = ffma2(chi2, va.x, l4hi[0]);
            l4lo[1] = ffma2(clo2, va.y, l4lo[1]); l4hi[1] = ffma2(chi2, va.y, l4hi[1]);
            l4lo[2] = ffma2(clo2, vb.x, l4lo[2]); l4hi[2] = ffma2(chi2, vb.x, l4hi[2]);
            l4lo[3] = ffma2(clo2, vb.y, l4lo[3]); l4hi[3] = ffma2(chi2, vb.y, l4hi[3]);
            l4lo[4] = ffma2(clo2, vc,   l4lo[4]); l4hi[4] = ffma2(chi2, vc,   l4hi[4]);
        }
    }

    // ---- export: tables + the L4 half the OTHER CTA merges ----
    float* blkMine  = g_part + (size_t)(2 * b + c) * PBLK;
    const float* blkOther = g_part + (size_t)(2 * b + (c ^ 1)) * PBLK;
    float lo, hi;
    if (active) {
        if (i2 == 0 && i3 == 0) {
            unpack2(l1v2, lo, hi);
            blkMine[i1] = lo; blkMine[i1 + 5] = hi;
        }
        if (i3 == 0) {
            unpack2(l2v2, lo, hi);
            blkMine[10 + i1 * 10 + i2] = lo;
            blkMine[10 + (i1 + 5) * 10 + i2] = hi;
        }
        unpack2(l3_2, lo, hi);
        blkMine[110 + tid] = lo;
        blkMine[110 + tid + 500] = hi;
        u64* e4 = reinterpret_cast<u64*>(blkMine + 1110);
#pragma unroll
        for (int j = 0; j < 5; ++j)
            e4[j * 500 + tid] = (c == 0) ? l4hi[j] : l4lo[j];
    }
    __threadfence();
    __syncthreads();
    if (tid == 0) {
        asm volatile("st.release.gpu.global.b32 [%0], %1;"
                     :: "l"(g_flag + 2 * b + c), "r"(1) : "memory");
    }

    // CTA1 stashes its own tables in smem for its merge
    if (c == 1 && active) {
        if (i2 == 0 && i3 == 0) {
            unpack2(l1v2, lo, hi);
            Ot[i1] = lo; Ot[i1 + 5] = hi;
        }
        if (i3 == 0) {
            unpack2(l2v2, lo, hi);
            Ot[10 + i1 * 10 + i2] = lo;
            Ot[10 + (i1 + 5) * 10 + i2] = hi;
        }
        unpack2(l3_2, lo, hi);
        Ot[110 + tid] = lo;
        Ot[110 + tid + 500] = hi;
    }

    // ---- spin on the other's flag, reset for graph replay ----
    if (tid == 0) {
        unsigned f;
        do {
            asm volatile("ld.acquire.gpu.global.b32 %0, [%1];"
                         : "=r"(f) : "l"(g_flag + 2 * b + (c ^ 1)) : "memory");
        } while (f == 0);
        asm volatile("st.relaxed.gpu.global.b32 [%0], %1;"
                     :: "l"(g_flag + 2 * b + (c ^ 1)), "r"(0) : "memory");
    }
    __syncthreads();

    // load the other chunk's tables (coalesced)
    for (int i = tid; i < 1110; i += 512) At[i] = blkOther[i];
    __syncthreads();

    float* ob = out + (size_t)b * SIG_OUT;

    if (c == 0) {
        // ---- CTA A merges rows [0,500) using its lo registers ----
        if (active) {
            const u64* B4p = reinterpret_cast<const u64*>(blkOther + 1110);
            u64 b4[5];
#pragma unroll
            for (int j = 0; j < 5; ++j) b4[j] = B4p[j * 500 + tid];
            float a1, xhi; unpack2(l1v2, a1, xhi);
            float a2; unpack2(l2v2, a2, xhi);
            float a3; unpack2(l3_2, a3, xhi);

            // level 3 lower
            stage[tid] = a3 + At[110 + tid] + a2 * At[i3] + a1 * At[10 + i2 * 10 + i3];

            // level 4 lower
            const u64* B1q = reinterpret_cast<const u64*>(At);
            const u64* B2q = reinterpret_cast<const u64*>(At + 10 + i3 * 10);
            const u64* B3q = reinterpret_cast<const u64*>(At + 110 + i2 * 100 + i3 * 10);
            u64 a1_2 = pack2(a1, a1), a2_2 = pack2(a2, a2), a3_2 = pack2(a3, a3);
            u64* s4 = reinterpret_cast<u64*>(stage + 500) + (size_t)tid * 5;
#pragma unroll
            for (int j = 0; j < 5; ++j) {
                u64 s = fadd2(l4lo[j], b4[j]);
                s = ffma2(a3_2, B1q[j], s);
                s = ffma2(a2_2, B2q[j], s);
                s = ffma2(a1_2, B3q[j], s);
                s4[j] = s;
            }
        }
        __syncthreads();
        // out[110,610) = L3 lower ; out[1110,6110) = L4 lower
        const u64* sp = reinterpret_cast<const u64*>(stage);
        u64* op = reinterpret_cast<u64*>(ob + 110);
        for (int i = tid; i < 250; i += 512) op[i] = sp[i];
        const u64* sp4 = reinterpret_cast<const u64*>(stage + 500);
        u64* op4 = reinterpret_cast<u64*>(ob + 1110);
        for (int i = tid; i < 2500; i += 512) op4[i] = sp4[i];
    } else {
        // ---- CTA B merges rows [500,1000) using its hi registers ----
        if (active) {
            const u64* A4p = reinterpret_cast<const u64*>(blkOther + 1110);
            u64 a4[5];
#pragma unroll
            for (int j = 0; j < 5; ++j) a4[j] = A4p[j * 500 + tid];
            float a1 = At[i1 + 5];
            float a2 = At[10 + (i1 + 5) * 10 + i2];
            float a3 = At[110 + 500 + tid];
            float xlo, b3; unpack2(l3_2, xlo, b3);

            // level 3 upper
            stage[110 + tid] = a3 + b3 + a2 * Ot[i3] + a1 * Ot[10 + i2 * 10 + i3];

            // level 4 upper
            const u64* B1q = reinterpret_cast<const u64*>(Ot);
            const u64* B2q = reinterpret_cast<const u64*>(Ot + 10 + i3 * 10);
            const u64* B3q = reinterpret_cast<const u64*>(Ot + 110 + i2 * 100 + i3 * 10);
            u64 a1_2 = pack2(a1, a1), a2_2 = pack2(a2, a2), a3_2 = pack2(a3, a3);
            u64* s4 = reinterpret_cast<u64*>(stage + 610) + (size_t)tid * 5;
#pragma unroll
            for (int j = 0; j < 5; ++j) {
                u64 s = fadd2(a4[j], l4hi[j]);
                s = ffma2(a3_2, B1q[j], s);
                s = ffma2(a2_2, B2q[j], s);
                s = ffma2(a1_2, B3q[j], s);
                s4[j] = s;
            }
        }
        // head (levels 1+2)
        if (tid < 110) {
            if (tid < 10) {
                stage[tid] = At[tid] + Ot[tid];
            } else {
                int m = tid - 10;
                stage[tid] = At[10 + m] + Ot[10 + m] + At[m / 10] * Ot[m % 10];
            }
        }
        __syncthreads();
        // out[0,110) head ; out[610,1110) L3 upper ; out[6110,11110) L4 upper
        const u64* sp = reinterpret_cast<const u64*>(stage);
        u64* op = reinterpret_cast<u64*>(ob);
        for (int i = tid; i < 55; i += 512) op[i] = sp[i];
        const u64* sp3 = reinterpret_cast<const u64*>(stage + 110);
        u64* op3 = reinterpret_cast<u64*>(ob + 610);
        for (int i = tid; i < 250; i += 512) op3[i] = sp3[i];
        const u64* sp4 = reinterpret_cast<const u64*>(stage + 610);
        u64* op4 = reinterpret_cast<u64*>(ob + 6110);
        for (int i = tid; i < 2500; i += 512) op4[i] = sp4[i];
    }
}

extern "C" void kernel_launch(void* const* d_in, const int* in_sizes, int n_in,
                              void* d_out, int out_size) {
    const float* path = (const float*)d_in[0];
    float* out = (float*)d_out;
    int B = in_sizes[0] / (SIG_L * SIG_C);
    if (B > SIG_MAXB) B = SIG_MAXB;
    sig_fused_kernel<<<B * 2, 512>>>(path, out);
}

// round 16
// speedup vs baseline: 1.1344x; 1.1344x over previous
#include <cuda_runtime.h>

// Depth-4 path signature, C=10, L=512. Two kernels (R12 structure):
//  K1 scan: R12 loop with one surgical change — a duplicated-dx table
//    dxd[(dx_k,dx_k) x10, 80B/step] supplies B2/C2 as LDS.64 and
//    d23_2 = fmul2(B2,C2), removing ~4 FMA-pipe ops (MOV splats) per step.
//    L4 partials stored TRANSPOSED (u64 at j*1000+p) -> coalesced.
//  K2 combine: VERBATIM R12 (2 CTAs/batch, coalesced, smem-staged).

#define SIG_C 10
#define SIG_L 512
#define SIG_NSTEP 511
#define SIG_OUT 11110
#define SIG_MAXB 128
#define CHUNK0 256

typedef unsigned long long u64;

// per chunk partial: [0,110) L1|L2, [110,1110) L3, [1110,11110) L4 transposed
__device__ __align__(16) float g_part[SIG_MAXB * 2 * SIG_OUT];

__device__ __forceinline__ u64 ffma2(u64 a, u64 b, u64 c) {
    u64 d; asm("fma.rn.f32x2 %0, %1, %2, %3;" : "=l"(d) : "l"(a), "l"(b), "l"(c)); return d;
}
__device__ __forceinline__ u64 fmul2(u64 a, u64 b) {
    u64 d; asm("mul.rn.f32x2 %0, %1, %2;" : "=l"(d) : "l"(a), "l"(b)); return d;
}
__device__ __forceinline__ u64 fadd2(u64 a, u64 b) {
    u64 d; asm("add.rn.f32x2 %0, %1, %2;" : "=l"(d) : "l"(a), "l"(b)); return d;
}
__device__ __forceinline__ u64 pack2(float lo, float hi) {
    u64 d; asm("mov.b64 %0, {%1, %2};" : "=l"(d) : "f"(lo), "f"(hi)); return d;
}
__device__ __forceinline__ void unpack2(u64 a, float& lo, float& hi) {
    asm("mov.b64 {%0, %1}, %2;" : "=f"(lo), "=f"(hi) : "l"(a));
}

// ---------------- Kernel 1: per-chunk signature scan -----------------------
__global__ __launch_bounds__(512, 1)
void sig_scan_kernel(const float* __restrict__ path) {
    __shared__ __align__(16) float dxs[CHUNK0 * 12];   // vector rows, 48B/step
    __shared__ __align__(16) float dxd[CHUNK0 * 20];   // (dx,dx) pairs, 80B/step

    const int b = blockIdx.x >> 1;
    const int c = blockIdx.x & 1;
    const int start = c ? CHUNK0 : 0;
    const int n = c ? (SIG_NSTEP - CHUNK0) : CHUNK0;   // 255 : 256
    const int tid = threadIdx.x;
    const float* prow = path + (size_t)b * SIG_L * SIG_C + (size_t)start * SIG_C;

    for (int i = tid; i < n * SIG_C; i += 512) {
        int t = i / SIG_C;
        int k = i - t * SIG_C;
        float v = prow[(t + 1) * SIG_C + k] - prow[t * SIG_C + k];
        dxs[t * 12 + k] = v;
        dxd[t * 20 + 2 * k]     = v;
        dxd[t * 20 + 2 * k + 1] = v;
    }
    __syncthreads();

    if (tid >= 500) return;
    const int i1 = tid / 100;          // 0..4 ; hi chain uses i1+5
    const int i2 = (tid / 10) % 10;
    const int i3 = tid % 10;

    const u64 c1_2  = pack2(0.5f, 0.5f);
    const u64 c1_6  = pack2(1.0f / 6.0f, 1.0f / 6.0f);
    const u64 c1_24 = pack2(1.0f / 24.0f, 1.0f / 24.0f);

    u64 l1v2, l2v2, l3_2;
    u64 l4lo[5], l4hi[5];
    {
        u64 B2 = *reinterpret_cast<const u64*>(dxd + 2 * i2);
        u64 C2 = *reinterpret_cast<const u64*>(dxd + 2 * i3);
        u64 A2 = pack2(dxs[i1], dxs[i1 + 5]);
        u64 d23_2 = fmul2(B2, C2);
        l1v2 = A2;
        l2v2 = fmul2(fmul2(A2, B2), c1_2);
        l3_2 = fmul2(fmul2(A2, d23_2), c1_6);
        u64 c4 = fmul2(l3_2, pack2(0.25f, 0.25f));
        float clo, chi; unpack2(c4, clo, chi);
        u64 clo2 = pack2(clo, clo), chi2 = pack2(chi, chi);
        ulonglong2 va = *reinterpret_cast<const ulonglong2*>(dxs);
        ulonglong2 vb = *reinterpret_cast<const ulonglong2*>(dxs + 4);
        u64 vc = *reinterpret_cast<const u64*>(dxs + 8);
        l4lo[0] = fmul2(clo2, va.x); l4hi[0] = fmul2(chi2, va.x);
        l4lo[1] = fmul2(clo2, va.y); l4hi[1] = fmul2(chi2, va.y);
        l4lo[2] = fmul2(clo2, vb.x); l4hi[2] = fmul2(chi2, vb.x);
        l4lo[3] = fmul2(clo2, vb.y); l4hi[3] = fmul2(chi2, vb.y);
        l4lo[4] = fmul2(clo2, vc);   l4hi[4] = fmul2(chi2, vc);
    }

    const float* q1 = dxs + i1 + 12;
    const char*  db = reinterpret_cast<const char*>(dxd) + 8 * i2 + 80;
    const char*  dc = reinterpret_cast<const char*>(dxd) + 8 * i3 + 80;
    const char*  qv = reinterpret_cast<const char*>(dxs) + 48;

#pragma unroll 4
    for (int t = 1; t < n; ++t) {
        float A_lo = *q1;
        float A_hi = q1[5];
        u64 B2 = *reinterpret_cast<const u64*>(db);
        u64 C2 = *reinterpret_cast<const u64*>(dc);
        ulonglong2 va = *reinterpret_cast<const ulonglong2*>(qv);
        ulonglong2 vb = *reinterpret_cast<const ulonglong2*>(qv + 16);
        u64 vc = *reinterpret_cast<const u64*>(qv + 32);
        q1 += 12; db += 80; dc += 80; qv += 48;

        u64 A2 = pack2(A_lo, A_hi);
        u64 d23_2 = fmul2(B2, C2);
        u64 t1 = fmul2(A2, d23_2);
        u64 uu = fmul2(l2v2, C2);
        u64 vv = fmul2(l1v2, d23_2);
        u64 coef = ffma2(c1_24, t1, ffma2(c1_2, uu, ffma2(c1_6, vv, l3_2)));
        l3_2 = ffma2(c1_6, t1, ffma2(c1_2, vv, fadd2(l3_2, uu)));
        l2v2 = ffma2(ffma2(c1_2, A2, l1v2), B2, l2v2);
        l1v2 = fadd2(l1v2, A2);

        float clo, chi; unpack2(coef, clo, chi);
        u64 clo2 = pack2(clo, clo), chi2 = pack2(chi, chi);
        l4lo[0] = ffma2(clo2, va.x, l4lo[0]); l4hi[0] = ffma2(chi2, va.x, l4hi[0]);
        l4lo[1] = ffma2(clo2, va.y, l4lo[1]); l4hi[1] = ffma2(chi2, va.y, l4hi[1]);
        l4lo[2] = ffma2(clo2, vb.x, l4lo[2]); l4hi[2] = ffma2(chi2, vb.x, l4hi[2]);
        l4lo[3] = ffma2(clo2, vb.y, l4lo[3]); l4hi[3] = ffma2(chi2, vb.y, l4hi[3]);
        l4lo[4] = ffma2(clo2, vc,   l4lo[4]); l4hi[4] = ffma2(chi2, vc,   l4hi[4]);
    }

    // ---- write partial: L1/L2/L3 scalar, L4 transposed-coalesced ----
    float* dst = g_part + ((size_t)b * 2 + c) * SIG_OUT;
    float lo, hi;
    if (i2 == 0 && i3 == 0) {
        unpack2(l1v2, lo, hi);
        dst[i1] = lo; dst[i1 + 5] = hi;
    }
    if (i3 == 0) {
        unpack2(l2v2, lo, hi);
        dst[10 + i1 * 10 + i2] = lo;
        dst[10 + (i1 + 5) * 10 + i2] = hi;
    }
    unpack2(l3_2, lo, hi);
    dst[110 + tid] = lo;
    dst[110 + tid + 500] = hi;
    u64* d4 = reinterpret_cast<u64*>(dst + 1110);
#pragma unroll
    for (int j = 0; j < 5; ++j) {
        d4[j * 1000 + tid]       = l4lo[j];
        d4[j * 1000 + tid + 500] = l4hi[j];
    }
}

// ---------------- Kernel 2: Chen combine (VERBATIM R12) --------------------
// stage layout (floats): [0,110) head (h=0 only), [110,610) L3 slice,
//                        [610,5610) L4 slice (500 rows x 10)
__global__ __launch_bounds__(512, 1)
void sig_combine_kernel(float* __restrict__ out) {
    __shared__ __align__(16) float As1[10], As2[100];
    __shared__ __align__(16) float Bs1d[16];
    __shared__ __align__(16) float Bs2[100];
    __shared__ __align__(16) float Bs3[1000];
    __shared__ __align__(16) float stage[5610];

    const int b = blockIdx.x >> 1;
    const int h = blockIdx.x & 1;          // p-half
    const int tid = threadIdx.x;
    const float* a  = g_part + (size_t)(2 * b) * SIG_OUT;
    const float* bb = g_part + (size_t)(2 * b + 1) * SIG_OUT;

    for (int i = tid; i < 1000; i += 512) Bs3[i] = bb[110 + i];
    if (tid < 100) { As2[tid] = a[10 + tid]; Bs2[tid] = bb[10 + tid]; }
    if (tid < 16) Bs1d[tid] = (tid < 10) ? bb[tid] : 0.0f;
    if (tid >= 16 && tid < 26) As1[tid - 16] = a[tid - 16];
    __syncthreads();

    if (tid < 500) {
        const int p = h * 500 + tid;
        const int i1 = p / 100;
        const int i2 = (p / 10) % 10;
        const int i3 = p % 10;

        const u64* A4 = reinterpret_cast<const u64*>(a + 1110);
        const u64* B4 = reinterpret_cast<const u64*>(bb + 1110);
        u64 a4[5], b4[5];
#pragma unroll
        for (int j = 0; j < 5; ++j) a4[j] = A4[j * 1000 + p];
#pragma unroll
        for (int j = 0; j < 5; ++j) b4[j] = B4[j * 1000 + p];
        float a3 = a[110 + p];

        float a1 = As1[i1];
        float a2 = As2[i1 * 10 + i2];

        stage[110 + tid] = a3 + Bs3[p] + a2 * Bs1d[i3] + a1 * Bs2[i2 * 10 + i3];

        const u64* B1q = reinterpret_cast<const u64*>(Bs1d);
        const u64* B2q = reinterpret_cast<const u64*>(Bs2 + i3 * 10);
        const u64* B3q = reinterpret_cast<const u64*>(Bs3 + i2 * 100 + i3 * 10);
        u64 a1_2 = pack2(a1, a1);
        u64 a2_2 = pack2(a2, a2);
        u64 a3_2 = pack2(a3, a3);
        u64* s4 = reinterpret_cast<u64*>(stage + 610) + (size_t)tid * 5;
#pragma unroll
        for (int j = 0; j < 5; ++j) {
            u64 s = fadd2(a4[j], b4[j]);
            s = ffma2(a3_2, B1q[j], s);
            s = ffma2(a2_2, B2q[j], s);
            s = ffma2(a1_2, B3q[j], s);
            s4[j] = s;
        }
    }
    if (h == 0 && tid < 110) {
        if (tid < 10) {
            stage[tid] = As1[tid] + Bs1d[tid];
        } else {
            int m = tid - 10;
            stage[tid] = As2[m] + Bs2[m] + As1[m / 10] * Bs1d[m % 10];
        }
    }
    __syncthreads();

    float* ob = out + (size_t)b * SIG_OUT;
    if (h == 0) {
        const u64* sp = reinterpret_cast<const u64*>(stage);
        u64* op = reinterpret_cast<u64*>(ob);
        for (int i = tid; i < 305; i += 512) op[i] = sp[i];
        const u64* sp4 = reinterpret_cast<const u64*>(stage + 610);
        u64* op4 = reinterpret_cast<u64*>(ob + 1110);
        for (int i = tid; i < 2500; i += 512) op4[i] = sp4[i];
    } else {
        const u64* sp = reinterpret_cast<const u64*>(stage + 110);
        u64* op = reinterpret_cast<u64*>(ob + 610);
        for (int i = tid; i < 250; i += 512) op[i] = sp[i];
        const u64* sp4 = reinterpret_cast<const u64*>(stage + 610);
        u64* op4 = reinterpret_cast<u64*>(ob + 6110);
        for (int i = tid; i < 2500; i += 512) op4[i] = sp4[i];
    }
}

extern "C" void kernel_launch(void* const* d_in, const int* in_sizes, int n_in,
                              void* d_out, int out_size) {
    const float* path = (const float*)d_in[0];
    float* out = (float*)d_out;
    int B = in_sizes[0] / (SIG_L * SIG_C);
    if (B > SIG_MAXB) B = SIG_MAXB;
    sig_scan_kernel<<<B * 2, 512>>>(path);
    sig_combine_kernel<<<B * 2, 512>>>(out);
}